// round 1
// baseline (speedup 1.0000x reference)
#include <cuda_runtime.h>
#include <math.h>

#define N_ROWS 8192
#define DIM    512
#define TWO_N  16384

// ---------------- device scratch (no allocations allowed) ----------------
__device__ float g_mean[2][DIM];
__device__ float g_energy[2][DIM];
__device__ float g_var[2][DIM];
__device__ float g_kurt[2][DIM];
__device__ float g_skew[2][DIM];
__device__ float g_rownorm[TWO_N];
// 0: mmd sum, 1: sum log(p) source, 2: sum log(1-p) target, 3: adaptive weight
__device__ float g_acc[4];

// ---------------- init ----------------
__global__ void k_zero() {
    if (threadIdx.x < 4) g_acc[threadIdx.x] = 0.f;
}

// ---------------- per-column pass 1: mean + energy ----------------
// grid (16, 2), 256 threads. blockIdx.y selects tensor.
__global__ void k_colstats1(const float* __restrict__ s, const float* __restrict__ t) {
    int tensor = blockIdx.y;
    const float* X = tensor ? t : s;
    int lane = threadIdx.x & 31;
    int w    = threadIdx.x >> 5;
    int col  = blockIdx.x * 32 + lane;

    float s1 = 0.f, s2 = 0.f;
    for (int r = w; r < N_ROWS; r += 8) {
        float v = X[(size_t)r * DIM + col];
        s1 += v;
        s2 += v * v;
    }
    __shared__ float sh1[8][32];
    __shared__ float sh2[8][32];
    sh1[w][lane] = s1;
    sh2[w][lane] = s2;
    __syncthreads();
    if (threadIdx.x < 32) {
        float a = 0.f, b = 0.f;
#pragma unroll
        for (int i = 0; i < 8; i++) { a += sh1[i][threadIdx.x]; b += sh2[i][threadIdx.x]; }
        int c = blockIdx.x * 32 + threadIdx.x;
        g_mean[tensor][c]   = a / (float)N_ROWS;
        g_energy[tensor][c] = b / (float)N_ROWS;
    }
}

// ---------------- per-column pass 2: var / skew / kurt ----------------
__global__ void k_colstats2(const float* __restrict__ s, const float* __restrict__ t) {
    int tensor = blockIdx.y;
    const float* X = tensor ? t : s;
    int lane = threadIdx.x & 31;
    int w    = threadIdx.x >> 5;
    int col  = blockIdx.x * 32 + lane;

    float m = g_mean[tensor][col];
    float c2 = 0.f, c3 = 0.f, c4 = 0.f;
    for (int r = w; r < N_ROWS; r += 8) {
        float d  = X[(size_t)r * DIM + col] - m;
        float d2 = d * d;
        c2 += d2;
        c3 += d2 * d;
        c4 += d2 * d2;
    }
    __shared__ float sh2[8][32];
    __shared__ float sh3[8][32];
    __shared__ float sh4[8][32];
    sh2[w][lane] = c2; sh3[w][lane] = c3; sh4[w][lane] = c4;
    __syncthreads();
    if (threadIdx.x < 32) {
        float a2 = 0.f, a3 = 0.f, a4 = 0.f;
#pragma unroll
        for (int i = 0; i < 8; i++) { a2 += sh2[i][threadIdx.x]; a3 += sh3[i][threadIdx.x]; a4 += sh4[i][threadIdx.x]; }
        int c = blockIdx.x * 32 + threadIdx.x;
        float var = a2 / (float)(N_ROWS - 1);
        float den = sqrtf(var) + 1e-8f;
        float inv = 1.f / den;
        float inv3 = inv * inv * inv;
        g_var[tensor][c]  = var;
        g_skew[tensor][c] = a3 * inv3 / (float)N_ROWS;
        g_kurt[tensor][c] = a4 * inv3 * inv / (float)N_ROWS - 3.f;
    }
}

// ---------------- row squared norms of u = [s; t] ----------------
// grid 2048, 256 threads (warp per row)
__global__ void k_rownorm(const float* __restrict__ s, const float* __restrict__ t) {
    int row  = blockIdx.x * 8 + (threadIdx.x >> 5);
    int lane = threadIdx.x & 31;
    const float* X = (row < N_ROWS) ? (s + (size_t)row * DIM)
                                    : (t + (size_t)(row - N_ROWS) * DIM);
    float acc = 0.f;
    for (int c = lane; c < DIM; c += 32) { float v = X[c]; acc += v * v; }
#pragma unroll
    for (int o = 16; o; o >>= 1) acc += __shfl_xor_sync(0xffffffffu, acc, o);
    if (!lane) g_rownorm[row] = acc;
}

// ---------------- stat diffs + adaptive-weight MLP (1 block) ----------------
__global__ void k_statmlp(const float* __restrict__ wW1, const float* __restrict__ wb1,
                          const float* __restrict__ wW2, const float* __restrict__ wb2,
                          const float* __restrict__ wW3, const float* __restrict__ wb3,
                          float* __restrict__ out) {
    __shared__ float red[5][256];
    int tid = threadIdx.x;
    float l[5] = {0.f, 0.f, 0.f, 0.f, 0.f};
    for (int c = tid; c < DIM; c += 256) {
        l[0] += fabsf(g_mean[0][c]   - g_mean[1][c]);
        l[1] += fabsf(g_var[0][c]    - g_var[1][c]);
        l[2] += fabsf(g_kurt[0][c]   - g_kurt[1][c]);
        l[3] += fabsf(g_skew[0][c]   - g_skew[1][c]);
        l[4] += fabsf(g_energy[0][c] - g_energy[1][c]);
    }
#pragma unroll
    for (int k = 0; k < 5; k++) red[k][tid] = l[k];
    __syncthreads();
    for (int stride = 128; stride > 0; stride >>= 1) {
        if (tid < stride)
#pragma unroll
            for (int k = 0; k < 5; k++) red[k][tid] += red[k][tid + stride];
        __syncthreads();
    }
    __shared__ float diff[6];
    __shared__ float h1[32];
    __shared__ float h2[16];
    if (tid < 6) diff[tid] = (tid < 5) ? red[tid][0] / (float)DIM : 0.f;
    __syncthreads();
    if (tid < 32) {
        float a = wb1[tid];
#pragma unroll
        for (int k = 0; k < 6; k++) a += diff[k] * wW1[k * 32 + tid];
        h1[tid] = fmaxf(a, 0.f);
    }
    __syncthreads();
    if (tid < 16) {
        float a = wb2[tid];
#pragma unroll
        for (int k = 0; k < 32; k++) a += h1[k] * wW2[k * 16 + tid];
        h2[tid] = fmaxf(a, 0.f);
    }
    __syncthreads();
    if (tid == 0) {
        float z = wb3[0];
#pragma unroll
        for (int k = 0; k < 16; k++) z += h2[k] * wW3[k];
        float wgt = 1.f / (1.f + expf(-z));
        g_acc[3] = wgt;
        out[1] = wgt;
    }
}

// ---------------- domain discriminator MLP + BCE ----------------
// grid 1024 (16 rows per block), 256 threads
#define DR 16
__global__ void __launch_bounds__(256) k_disc(
    const float* __restrict__ s, const float* __restrict__ t,
    const float* __restrict__ W1, const float* __restrict__ b1,
    const float* __restrict__ W2, const float* __restrict__ b2,
    const float* __restrict__ W3, const float* __restrict__ b3) {
    __shared__ __align__(16) float smem[DR * DIM + DR * 256];  // 48KB
    float* xs = smem;                 // [DR][512]
    float* h1 = smem + DR * DIM;      // [DR][256]

    int tid = threadIdx.x;
    int blk = blockIdx.x;
    bool srcblk = blk < (N_ROWS / DR);   // 512 source blocks
    const float* X = srcblk ? (s + (size_t)blk * DR * DIM)
                            : (t + (size_t)(blk - N_ROWS / DR) * DR * DIM);
    for (int i = tid; i < DR * DIM; i += 256) xs[i] = X[i];
    __syncthreads();

    // layer 1: 512 -> 256
    {
        float acc[DR];
#pragma unroll
        for (int r = 0; r < DR; r++) acc[r] = 0.f;
        for (int k = 0; k < DIM; k += 4) {
            float w0 = W1[(k + 0) * 256 + tid];
            float w1 = W1[(k + 1) * 256 + tid];
            float w2 = W1[(k + 2) * 256 + tid];
            float w3 = W1[(k + 3) * 256 + tid];
#pragma unroll
            for (int r = 0; r < DR; r++) {
                float4 xv = *(const float4*)&xs[r * DIM + k];
                acc[r] += xv.x * w0 + xv.y * w1 + xv.z * w2 + xv.w * w3;
            }
        }
        float bb = b1[tid];
#pragma unroll
        for (int r = 0; r < DR; r++) h1[r * 256 + tid] = fmaxf(acc[r] + bb, 0.f);
    }
    __syncthreads();

    // layer 2: 256 -> 128 (h2 overlays xs region)
    float* h2 = smem;
    if (tid < 128) {
        float acc[DR];
#pragma unroll
        for (int r = 0; r < DR; r++) acc[r] = 0.f;
        for (int k = 0; k < 256; k += 4) {
            float w0 = W2[(k + 0) * 128 + tid];
            float w1 = W2[(k + 1) * 128 + tid];
            float w2 = W2[(k + 2) * 128 + tid];
            float w3 = W2[(k + 3) * 128 + tid];
#pragma unroll
            for (int r = 0; r < DR; r++) {
                float4 hv = *(const float4*)&h1[r * 256 + k];
                acc[r] += hv.x * w0 + hv.y * w1 + hv.z * w2 + hv.w * w3;
            }
        }
        float bb = b2[tid];
#pragma unroll
        for (int r = 0; r < DR; r++) h2[r * 128 + tid] = fmaxf(acc[r] + bb, 0.f);
    }
    __syncthreads();

    // layer 3: 128 -> 1, sigmoid, clamped BCE term. 8 warps x 2 rows each.
    int w = tid >> 5, lane = tid & 31;
    float lsum = 0.f;
#pragma unroll
    for (int rr = 0; rr < 2; rr++) {
        int r = w * 2 + rr;
        float v = 0.f;
#pragma unroll
        for (int k = lane; k < 128; k += 32) v += h2[r * 128 + k] * W3[k];
#pragma unroll
        for (int o = 16; o; o >>= 1) v += __shfl_xor_sync(0xffffffffu, v, o);
        if (!lane) {
            float z = v + b3[0];
            float p = 1.f / (1.f + expf(-z));
            float term = srcblk ? fmaxf(logf(p), -100.f)
                                : fmaxf(logf(1.f - p), -100.f);
            lsum += term;
        }
    }
    if (!lane) atomicAdd(&g_acc[srcblk ? 1 : 2], lsum);
}

// ---------------- MMD: upper-triangular signed Gram sum ----------------
// u = [s; t] (16384 x 512). sum = Sigma_{j>=i} w_ij * eps_i*eps_j * exp(-d2/2),
// w = 2 off-diag / 1 diag == full symmetric signed sum == N^2 * mmd.
#define BMM 128
#define BKK 16
__global__ void __launch_bounds__(256) k_mmd(const float* __restrict__ s,
                                             const float* __restrict__ t) {
    int by = blockIdx.y, bx = blockIdx.x;
    if (bx < by) return;  // upper triangle only

    __shared__ __align__(16) float As[BKK][BMM + 4];
    __shared__ __align__(16) float Bs[BKK][BMM + 4];

    int tid = threadIdx.x;
    int tx = tid & 15, ty = tid >> 4;

    const float* Ap = (by < 64) ? s : t;
    const float* Bp = (bx < 64) ? s : t;
    int arow0 = (by & 63) * BMM;
    int brow0 = (bx & 63) * BMM;

    float acc[8][8];
#pragma unroll
    for (int i = 0; i < 8; i++)
#pragma unroll
        for (int j = 0; j < 8; j++) acc[i][j] = 0.f;

    for (int kt = 0; kt < DIM; kt += BKK) {
#pragma unroll
        for (int q = 0; q < 2; q++) {
            int idx = tid + q * 256;      // 0..511
            int row = idx >> 2;
            int cg  = (idx & 3) * 4;
            float4 va = *(const float4*)&Ap[(size_t)(arow0 + row) * DIM + kt + cg];
            As[cg + 0][row] = va.x; As[cg + 1][row] = va.y;
            As[cg + 2][row] = va.z; As[cg + 3][row] = va.w;
            float4 vb = *(const float4*)&Bp[(size_t)(brow0 + row) * DIM + kt + cg];
            Bs[cg + 0][row] = vb.x; Bs[cg + 1][row] = vb.y;
            Bs[cg + 2][row] = vb.z; Bs[cg + 3][row] = vb.w;
        }
        __syncthreads();
#pragma unroll
        for (int k = 0; k < BKK; k++) {
            float a[8], b[8];
            float4 a0 = *(const float4*)&As[k][ty * 8];
            float4 a1 = *(const float4*)&As[k][ty * 8 + 4];
            float4 b0 = *(const float4*)&Bs[k][tx * 8];
            float4 b1 = *(const float4*)&Bs[k][tx * 8 + 4];
            a[0]=a0.x; a[1]=a0.y; a[2]=a0.z; a[3]=a0.w;
            a[4]=a1.x; a[5]=a1.y; a[6]=a1.z; a[7]=a1.w;
            b[0]=b0.x; b[1]=b0.y; b[2]=b0.z; b[3]=b0.w;
            b[4]=b1.x; b[5]=b1.y; b[6]=b1.z; b[7]=b1.w;
#pragma unroll
            for (int i = 0; i < 8; i++)
#pragma unroll
                for (int j = 0; j < 8; j++) acc[i][j] += a[i] * b[j];
        }
        __syncthreads();
    }

    // epilogue
    float sgn = ((by < 64) == (bx < 64)) ? 1.f : -1.f;
    bool diagtile = (bx == by);
    int gi0 = by * BMM + ty * 8;
    int gj0 = bx * BMM + tx * 8;
    float rni[8], rnj[8];
#pragma unroll
    for (int i = 0; i < 8; i++) { rni[i] = g_rownorm[gi0 + i]; rnj[i] = g_rownorm[gj0 + i]; }

    float local = 0.f;
#pragma unroll
    for (int i = 0; i < 8; i++) {
#pragma unroll
        for (int j = 0; j < 8; j++) {
            float d2 = rni[i] + rnj[j] - 2.f * acc[i][j];
            float f = 2.f;
            if (diagtile) {
                int d = (gj0 + j) - (gi0 + i);
                f = (d > 0) ? 2.f : ((d == 0) ? 1.f : 0.f);
            }
            // fp32 exp(-d2/2) is exactly 0 beyond this threshold; terms in
            // [160,208) are < 2e-35 each — below representable effect on mmd.
            if (f != 0.f && d2 < 160.f) {
                local += sgn * f * expf(-0.5f * d2);
            }
        }
    }
#pragma unroll
    for (int o = 16; o; o >>= 1) local += __shfl_xor_sync(0xffffffffu, local, o);
    __shared__ float rsum[8];
    if (!(tid & 31)) rsum[tid >> 5] = local;
    __syncthreads();
    if (tid == 0) {
        float tot = 0.f;
#pragma unroll
        for (int i = 0; i < 8; i++) tot += rsum[i];
        if (tot != 0.f) atomicAdd(&g_acc[0], tot);
    }
}

// ---------------- final combine ----------------
__global__ void k_final(float* __restrict__ out) {
    float mmd  = g_acc[0] / ((float)N_ROWS * (float)N_ROWS);
    float bsrc = -g_acc[1] / (float)N_ROWS;
    float btgt = -g_acc[2] / (float)N_ROWS;
    float adv  = bsrc + btgt;
    float w    = g_acc[3];
    out[0] = w * mmd + (1.f - w) * adv;
}

// ---------------- launch ----------------
extern "C" void kernel_launch(void* const* d_in, const int* in_sizes, int n_in,
                              void* d_out, int out_size) {
    const float* s   = (const float*)d_in[0];
    const float* t   = (const float*)d_in[1];
    const float* dW1 = (const float*)d_in[2];
    const float* db1 = (const float*)d_in[3];
    const float* dW2 = (const float*)d_in[4];
    const float* db2 = (const float*)d_in[5];
    const float* dW3 = (const float*)d_in[6];
    const float* db3 = (const float*)d_in[7];
    const float* wW1 = (const float*)d_in[8];
    const float* wb1 = (const float*)d_in[9];
    const float* wW2 = (const float*)d_in[10];
    const float* wb2 = (const float*)d_in[11];
    const float* wW3 = (const float*)d_in[12];
    const float* wb3 = (const float*)d_in[13];
    float* out = (float*)d_out;

    k_zero<<<1, 32>>>();
    k_colstats1<<<dim3(16, 2), 256>>>(s, t);
    k_rownorm<<<TWO_N / 8, 256>>>(s, t);
    k_colstats2<<<dim3(16, 2), 256>>>(s, t);
    k_statmlp<<<1, 256>>>(wW1, wb1, wW2, wb2, wW3, wb3, out);
    k_disc<<<TWO_N / DR, 256>>>(s, t, dW1, db1, dW2, db2, dW3, db3);
    k_mmd<<<dim3(128, 128), 256>>>(s, t);
    k_final<<<1, 1>>>(out);
}

// round 3
// speedup vs baseline: 3.8630x; 3.8630x over previous
#include <cuda_runtime.h>
#include <cuda_bf16.h>
#include <math.h>
#include <stdint.h>

#define N_ROWS 8192
#define DIM    512
#define TWO_N  16384

// ================= device scratch =================
__device__ float g_mean[2][DIM];
__device__ float g_energy[2][DIM];
__device__ float g_var[2][DIM];
__device__ float g_kurt[2][DIM];
__device__ float g_skew[2][DIM];
__device__ float g_rownorm[TWO_N];
__device__ float g_cacc[2][5][DIM];          // atomic partials: sum, sumsq, c2, c3, c4
__device__ float g_acc[4];                   // 0 mmd-sum, 1 log(p) src, 2 log(1-p) tgt, 3 weight
__device__ __nv_bfloat16 g_ubf[(size_t)TWO_N * DIM];

// ================= helpers =================
__device__ __forceinline__ void cp16(uint32_t dst_smem, const void* src) {
    asm volatile("cp.async.cg.shared.global [%0], [%1], 16;" :: "r"(dst_smem), "l"(src));
}
__device__ __forceinline__ void mma16816(float* c, const uint32_t* a, const uint32_t* b) {
    asm volatile(
        "mma.sync.aligned.m16n8k16.row.col.f32.bf16.bf16.f32 "
        "{%0,%1,%2,%3}, {%4,%5,%6,%7}, {%8,%9}, {%0,%1,%2,%3};"
        : "+f"(c[0]), "+f"(c[1]), "+f"(c[2]), "+f"(c[3])
        : "r"(a[0]), "r"(a[1]), "r"(a[2]), "r"(a[3]), "r"(b[0]), "r"(b[1]));
}

// ================= init =================
__global__ void k_zero() {
    float* p = &g_cacc[0][0][0];
    for (int i = blockIdx.x * blockDim.x + threadIdx.x; i < 2 * 5 * DIM; i += gridDim.x * blockDim.x)
        p[i] = 0.f;
    if (blockIdx.x == 0 && threadIdx.x < 4) g_acc[threadIdx.x] = 0.f;
}

// ================= fp32 -> bf16 convert (u = [s; t]) =================
__global__ void k_convert(const float* __restrict__ s, const float* __restrict__ t) {
    size_t i = (size_t)blockIdx.x * blockDim.x + threadIdx.x;   // float4 index
    const size_t HALF = (size_t)N_ROWS * DIM / 4;
    float4 v = (i < HALF) ? ((const float4*)s)[i] : ((const float4*)t)[i - HALF];
    __nv_bfloat162 lo = __floats2bfloat162_rn(v.x, v.y);
    __nv_bfloat162 hi = __floats2bfloat162_rn(v.z, v.w);
    ((__nv_bfloat162*)g_ubf)[2 * i]     = lo;
    ((__nv_bfloat162*)g_ubf)[2 * i + 1] = hi;
}

// ================= column stats pass 1 =================
__global__ void k_colstats1(const float* __restrict__ s, const float* __restrict__ t) {
    int tensor = blockIdx.z;
    const float* X = tensor ? t : s;
    int lane = threadIdx.x & 31, w = threadIdx.x >> 5;
    int col = blockIdx.x * 32 + lane;
    int r0 = blockIdx.y * 1024;
    float s1 = 0.f, s2 = 0.f;
    for (int r = r0 + w; r < r0 + 1024; r += 8) {
        float v = X[(size_t)r * DIM + col];
        s1 += v; s2 += v * v;
    }
    __shared__ float sh1[8][32], sh2[8][32];
    sh1[w][lane] = s1; sh2[w][lane] = s2;
    __syncthreads();
    if (threadIdx.x < 32) {
        float a = 0.f, b = 0.f;
#pragma unroll
        for (int i = 0; i < 8; i++) { a += sh1[i][threadIdx.x]; b += sh2[i][threadIdx.x]; }
        int c = blockIdx.x * 32 + threadIdx.x;
        atomicAdd(&g_cacc[tensor][0][c], a);
        atomicAdd(&g_cacc[tensor][1][c], b);
    }
}

__global__ void k_colmean() {
    int tensor = blockIdx.x, c = threadIdx.x;
    g_mean[tensor][c]   = g_cacc[tensor][0][c] / (float)N_ROWS;
    g_energy[tensor][c] = g_cacc[tensor][1][c] / (float)N_ROWS;
}

// ================= column stats pass 2 =================
__global__ void k_colstats2(const float* __restrict__ s, const float* __restrict__ t) {
    int tensor = blockIdx.z;
    const float* X = tensor ? t : s;
    int lane = threadIdx.x & 31, w = threadIdx.x >> 5;
    int col = blockIdx.x * 32 + lane;
    int r0 = blockIdx.y * 1024;
    float m = g_mean[tensor][col];
    float c2 = 0.f, c3 = 0.f, c4 = 0.f;
    for (int r = r0 + w; r < r0 + 1024; r += 8) {
        float d = X[(size_t)r * DIM + col] - m;
        float d2 = d * d;
        c2 += d2; c3 += d2 * d; c4 += d2 * d2;
    }
    __shared__ float sh2[8][32], sh3[8][32], sh4[8][32];
    sh2[w][lane] = c2; sh3[w][lane] = c3; sh4[w][lane] = c4;
    __syncthreads();
    if (threadIdx.x < 32) {
        float a2 = 0.f, a3 = 0.f, a4 = 0.f;
#pragma unroll
        for (int i = 0; i < 8; i++) { a2 += sh2[i][threadIdx.x]; a3 += sh3[i][threadIdx.x]; a4 += sh4[i][threadIdx.x]; }
        int c = blockIdx.x * 32 + threadIdx.x;
        atomicAdd(&g_cacc[tensor][2][c], a2);
        atomicAdd(&g_cacc[tensor][3][c], a3);
        atomicAdd(&g_cacc[tensor][4][c], a4);
    }
}

__global__ void k_colfin() {
    int tensor = blockIdx.x, c = threadIdx.x;
    float var = g_cacc[tensor][2][c] / (float)(N_ROWS - 1);
    float inv = 1.f / (sqrtf(var) + 1e-8f);
    float inv3 = inv * inv * inv;
    g_var[tensor][c]  = var;
    g_skew[tensor][c] = g_cacc[tensor][3][c] * inv3 / (float)N_ROWS;
    g_kurt[tensor][c] = g_cacc[tensor][4][c] * inv3 * inv / (float)N_ROWS - 3.f;
}

// ================= row squared norms =================
__global__ void k_rownorm(const float* __restrict__ s, const float* __restrict__ t) {
    int row = blockIdx.x * 8 + (threadIdx.x >> 5);
    int lane = threadIdx.x & 31;
    const float4* X = (row < N_ROWS) ? (const float4*)(s + (size_t)row * DIM)
                                     : (const float4*)(t + (size_t)(row - N_ROWS) * DIM);
    float acc = 0.f;
#pragma unroll
    for (int i = 0; i < 4; i++) {
        float4 v = X[lane + i * 32];
        acc += v.x * v.x + v.y * v.y + v.z * v.z + v.w * v.w;
    }
#pragma unroll
    for (int o = 16; o; o >>= 1) acc += __shfl_xor_sync(0xffffffffu, acc, o);
    if (!lane) g_rownorm[row] = acc;
}

// ================= stat-diff MLP =================
__global__ void k_statmlp(const float* __restrict__ wW1, const float* __restrict__ wb1,
                          const float* __restrict__ wW2, const float* __restrict__ wb2,
                          const float* __restrict__ wW3, const float* __restrict__ wb3,
                          float* __restrict__ out) {
    __shared__ float red[5][256];
    int tid = threadIdx.x;
    float l[5] = {0.f, 0.f, 0.f, 0.f, 0.f};
    for (int c = tid; c < DIM; c += 256) {
        l[0] += fabsf(g_mean[0][c]   - g_mean[1][c]);
        l[1] += fabsf(g_var[0][c]    - g_var[1][c]);
        l[2] += fabsf(g_kurt[0][c]   - g_kurt[1][c]);
        l[3] += fabsf(g_skew[0][c]   - g_skew[1][c]);
        l[4] += fabsf(g_energy[0][c] - g_energy[1][c]);
    }
#pragma unroll
    for (int k = 0; k < 5; k++) red[k][tid] = l[k];
    __syncthreads();
    for (int stride = 128; stride > 0; stride >>= 1) {
        if (tid < stride)
#pragma unroll
            for (int k = 0; k < 5; k++) red[k][tid] += red[k][tid + stride];
        __syncthreads();
    }
    __shared__ float diff[6], h1[32], h2[16];
    if (tid < 6) diff[tid] = (tid < 5) ? red[tid][0] / (float)DIM : 0.f;
    __syncthreads();
    if (tid < 32) {
        float a = wb1[tid];
#pragma unroll
        for (int k = 0; k < 6; k++) a += diff[k] * wW1[k * 32 + tid];
        h1[tid] = fmaxf(a, 0.f);
    }
    __syncthreads();
    if (tid < 16) {
        float a = wb2[tid];
#pragma unroll
        for (int k = 0; k < 32; k++) a += h1[k] * wW2[k * 16 + tid];
        h2[tid] = fmaxf(a, 0.f);
    }
    __syncthreads();
    if (tid == 0) {
        float z = wb3[0];
#pragma unroll
        for (int k = 0; k < 16; k++) z += h2[k] * wW3[k];
        float wgt = 1.f / (1.f + expf(-z));
        g_acc[3] = wgt;
        out[1] = wgt;
    }
}

// ================= discriminator MLP + BCE =================
#define DR 32
__global__ void __launch_bounds__(256) k_disc(
    const float* __restrict__ s, const float* __restrict__ t,
    const float* __restrict__ W1, const float* __restrict__ b1,
    const float* __restrict__ W2, const float* __restrict__ b2,
    const float* __restrict__ W3, const float* __restrict__ b3) {
    extern __shared__ float dsm[];
    float* xs = dsm;                  // [DR][512]
    float* h1 = dsm + DR * DIM;       // [DR][256]

    int tid = threadIdx.x;
    int blk = blockIdx.x;
    bool srcblk = blk < (N_ROWS / DR);
    const float* X = srcblk ? (s + (size_t)blk * DR * DIM)
                            : (t + (size_t)(blk - N_ROWS / DR) * DR * DIM);
    for (int i = tid; i < DR * DIM / 4; i += 256)
        ((float4*)xs)[i] = ((const float4*)X)[i];
    __syncthreads();

    // layer 1: 512 -> 256
    {
        float acc[DR];
#pragma unroll
        for (int r = 0; r < DR; r++) acc[r] = 0.f;
        for (int k = 0; k < DIM; k += 4) {
            float w0 = W1[(k + 0) * 256 + tid];
            float w1 = W1[(k + 1) * 256 + tid];
            float w2 = W1[(k + 2) * 256 + tid];
            float w3 = W1[(k + 3) * 256 + tid];
#pragma unroll
            for (int r = 0; r < DR; r++) {
                float4 xv = *(const float4*)&xs[r * DIM + k];
                acc[r] += xv.x * w0 + xv.y * w1 + xv.z * w2 + xv.w * w3;
            }
        }
        float bb = b1[tid];
#pragma unroll
        for (int r = 0; r < DR; r++) h1[r * 256 + tid] = fmaxf(acc[r] + bb, 0.f);
    }
    __syncthreads();

    // layer 2: 256 -> 128 (h2 overlays xs)
    float* h2 = dsm;
    if (tid < 128) {
        float acc[DR];
#pragma unroll
        for (int r = 0; r < DR; r++) acc[r] = 0.f;
        for (int k = 0; k < 256; k += 4) {
            float w0 = W2[(k + 0) * 128 + tid];
            float w1 = W2[(k + 1) * 128 + tid];
            float w2 = W2[(k + 2) * 128 + tid];
            float w3 = W2[(k + 3) * 128 + tid];
#pragma unroll
            for (int r = 0; r < DR; r++) {
                float4 hv = *(const float4*)&h1[r * 256 + k];
                acc[r] += hv.x * w0 + hv.y * w1 + hv.z * w2 + hv.w * w3;
            }
        }
        float bb = b2[tid];
#pragma unroll
        for (int r = 0; r < DR; r++) h2[r * 128 + tid] = fmaxf(acc[r] + bb, 0.f);
    }
    __syncthreads();

    // layer 3: 128 -> 1 + sigmoid + clamped log; 8 warps x 4 rows
    int w = tid >> 5, lane = tid & 31;
    float lsum = 0.f;
#pragma unroll
    for (int rr = 0; rr < 4; rr++) {
        int r = w * 4 + rr;
        float v = 0.f;
#pragma unroll
        for (int k = lane; k < 128; k += 32) v += h2[r * 128 + k] * W3[k];
#pragma unroll
        for (int o = 16; o; o >>= 1) v += __shfl_xor_sync(0xffffffffu, v, o);
        if (!lane) {
            float z = v + b3[0];
            float p = 1.f / (1.f + expf(-z));
            lsum += srcblk ? fmaxf(logf(p), -100.f) : fmaxf(logf(1.f - p), -100.f);
        }
    }
    if (!lane) atomicAdd(&g_acc[srcblk ? 1 : 2], lsum);
}

// ================= MMD via mma.sync bf16 Gram (upper triangle) =================
// CTA 128x128 tile, 8 warps (2x4), warp tile 64x32, BK=32 double-buffered cp.async.
#define AST 40   // smem row stride in bf16 elements (80 B: 16B-aligned, conflict-free)

__global__ void __launch_bounds__(256, 2) k_mmd_hmma(const float* __restrict__ s,
                                                     const float* __restrict__ t) {
    int by = blockIdx.y, bx = blockIdx.x;
    if (bx < by) return;                     // upper triangle only

    __shared__ __nv_bfloat16 As[2][128 * AST];
    __shared__ __nv_bfloat16 Bs[2][128 * AST];
    __shared__ float rni_s[128], rnj_s[128], rsum[8];

    int tid = threadIdx.x, lane = tid & 31, wid = tid >> 5;
    int wm = wid & 1, wn = wid >> 1;         // warp grid 2 (M) x 4 (N)
    int gid = lane >> 2, tig = lane & 3;
    int arow0 = by * 128, brow0 = bx * 128;

    if (tid < 128) {
        rni_s[tid] = g_rownorm[arow0 + tid];
        rnj_s[tid] = g_rownorm[brow0 + tid];
    }

    uint32_t sA = (uint32_t)__cvta_generic_to_shared(&As[0][0]);
    uint32_t sB = (uint32_t)__cvta_generic_to_shared(&Bs[0][0]);
    const __nv_bfloat16* gA = g_ubf + (size_t)arow0 * DIM;
    const __nv_bfloat16* gB = g_ubf + (size_t)brow0 * DIM;

    float acc[4][4][4];
#pragma unroll
    for (int i = 0; i < 4; i++)
#pragma unroll
        for (int j = 0; j < 4; j++)
#pragma unroll
            for (int e = 0; e < 4; e++) acc[i][j][e] = 0.f;

    // ---- async-copy one BK=32 stage ----
    auto issue = [&](int kt, int st) {
#pragma unroll
        for (int q = 0; q < 2; q++) {
            int c = tid + q * 256;           // 0..511 16B-chunks
            int row = c >> 2, cg = c & 3;
            size_t goff = (size_t)row * DIM + (size_t)kt * 32 + cg * 8;
            uint32_t soff = (uint32_t)(st * (128 * AST * 2) + row * (AST * 2) + cg * 16);
            cp16(sA + soff, gA + goff);
            cp16(sB + soff, gB + goff);
        }
        asm volatile("cp.async.commit_group;" ::: "memory");
    };

    issue(0, 0);
    for (int kt = 0; kt < 16; kt++) {
        int st = kt & 1;
        if (kt < 15) {
            issue(kt + 1, st ^ 1);
            asm volatile("cp.async.wait_group 1;" ::: "memory");
        } else {
            asm volatile("cp.async.wait_group 0;" ::: "memory");
        }
        __syncthreads();

        const __nv_bfloat16* Ast = As[st];
        const __nv_bfloat16* Bst = Bs[st];
#pragma unroll
        for (int ks = 0; ks < 2; ks++) {     // two k16 steps per BK=32
            int kb = ks * 16;
            uint32_t af[4][4], bf[4][2];
#pragma unroll
            for (int mt = 0; mt < 4; mt++) {
                const __nv_bfloat16* p = Ast + (wm * 64 + mt * 16 + gid) * AST + kb + 2 * tig;
                af[mt][0] = *(const uint32_t*)p;
                af[mt][1] = *(const uint32_t*)(p + 8 * AST);
                af[mt][2] = *(const uint32_t*)(p + 8);
                af[mt][3] = *(const uint32_t*)(p + 8 * AST + 8);
            }
#pragma unroll
            for (int nt = 0; nt < 4; nt++) {
                const __nv_bfloat16* p = Bst + (wn * 32 + nt * 8 + gid) * AST + kb + 2 * tig;
                bf[nt][0] = *(const uint32_t*)p;
                bf[nt][1] = *(const uint32_t*)(p + 8);
            }
#pragma unroll
            for (int mt = 0; mt < 4; mt++)
#pragma unroll
                for (int nt = 0; nt < 4; nt++)
                    mma16816(acc[mt][nt], af[mt], bf[nt]);
        }
        __syncthreads();
    }

    // ---- epilogue: gate + (rare) exact fp32 recompute ----
    bool diag = (bx == by);
    float sgn = ((by < 64) == (bx < 64)) ? 1.f : -1.f;
    float local = 0.f;

#pragma unroll
    for (int mt = 0; mt < 4; mt++) {
        int li0 = wm * 64 + mt * 16 + gid;          // local row of c0/c1
        float rn0 = rni_s[li0], rn1 = rni_s[li0 + 8];
#pragma unroll
        for (int nt = 0; nt < 4; nt++) {
            int lj0 = wn * 32 + nt * 8 + 2 * tig;   // local col of c0/c2
#pragma unroll
            for (int e = 0; e < 4; e++) {
                int li = li0 + ((e >= 2) ? 8 : 0);
                int lj = lj0 + (e & 1);
                float rn_i = (e >= 2) ? rn1 : rn0;
                float rj = rnj_s[lj];
                float dot = acc[mt][nt][e];
                float d2 = rn_i + rj - 2.f * dot;
                int gi = arow0 + li, gj = brow0 + lj;
                float wgt = diag ? ((gj > gi) ? 2.f : 0.f) : 2.f;
                if (wgt != 0.f && d2 < 110.f + 0.02f * (rn_i + rj)) {
                    // exact fp32 recompute (hit only by near-duplicate pairs)
                    const float* pi = (gi < N_ROWS) ? s + (size_t)gi * DIM
                                                    : t + (size_t)(gi - N_ROWS) * DIM;
                    const float* pj = (gj < N_ROWS) ? s + (size_t)gj * DIM
                                                    : t + (size_t)(gj - N_ROWS) * DIM;
                    float a2 = 0.f;
                    for (int k = 0; k < DIM; k += 4) {
                        float4 a = *(const float4*)(pi + k);
                        float4 b = *(const float4*)(pj + k);
                        float e0 = a.x - b.x, e1 = a.y - b.y, e2 = a.z - b.z, e3 = a.w - b.w;
                        a2 += e0 * e0 + e1 * e1 + e2 * e2 + e3 * e3;
                    }
                    local += wgt * expf(-0.5f * a2);
                }
            }
        }
    }
    local *= sgn;
#pragma unroll
    for (int o = 16; o; o >>= 1) local += __shfl_xor_sync(0xffffffffu, local, o);
    if (!lane) rsum[wid] = local;
    __syncthreads();
    if (tid == 0) {
        float tot = 0.f;
#pragma unroll
        for (int i = 0; i < 8; i++) tot += rsum[i];
        if (tot != 0.f) atomicAdd(&g_acc[0], tot);
    }
}

// ================= final combine =================
__global__ void k_final(float* __restrict__ out) {
    // + TWO_N: analytic diagonal (d2 == 0 -> exp == 1, weight 1, sign +)
    float mmd = (g_acc[0] + (float)TWO_N) / ((float)N_ROWS * (float)N_ROWS);
    float adv = -g_acc[1] / (float)N_ROWS - g_acc[2] / (float)N_ROWS;
    float w = g_acc[3];
    out[0] = w * mmd + (1.f - w) * adv;
}

// ================= launch =================
extern "C" void kernel_launch(void* const* d_in, const int* in_sizes, int n_in,
                              void* d_out, int out_size) {
    const float* s   = (const float*)d_in[0];
    const float* t   = (const float*)d_in[1];
    const float* dW1 = (const float*)d_in[2];
    const float* db1 = (const float*)d_in[3];
    const float* dW2 = (const float*)d_in[4];
    const float* db2 = (const float*)d_in[5];
    const float* dW3 = (const float*)d_in[6];
    const float* db3 = (const float*)d_in[7];
    const float* wW1 = (const float*)d_in[8];
    const float* wb1 = (const float*)d_in[9];
    const float* wW2 = (const float*)d_in[10];
    const float* wb2 = (const float*)d_in[11];
    const float* wW3 = (const float*)d_in[12];
    const float* wb3 = (const float*)d_in[13];
    float* out = (float*)d_out;

    static int disc_smem = (DR * DIM + DR * 256) * (int)sizeof(float);
    cudaFuncSetAttribute(k_disc, cudaFuncAttributeMaxDynamicSharedMemorySize, disc_smem);

    k_zero<<<8, 256>>>();
    k_convert<<<8192, 256>>>(s, t);
    k_colstats1<<<dim3(16, 8, 2), 256>>>(s, t);
    k_rownorm<<<TWO_N / 8, 256>>>(s, t);
    k_colmean<<<2, 512>>>();
    k_colstats2<<<dim3(16, 8, 2), 256>>>(s, t);
    k_colfin<<<2, 512>>>();
    k_statmlp<<<1, 256>>>(wW1, wb1, wW2, wb2, wW3, wb3, out);
    k_disc<<<TWO_N / DR, 256, disc_smem>>>(s, t, dW1, db1, dW2, db2, dW3, db3);
    k_mmd_hmma<<<dim3(128, 128), 256>>>(s, t);
    k_final<<<1, 1>>>(out);
}

// round 4
// speedup vs baseline: 3.9661x; 1.0267x over previous
#include <cuda_runtime.h>
#include <cuda_bf16.h>
#include <math.h>
#include <stdint.h>

#define N_ROWS 8192
#define DIM    512
#define TWO_N  16384

// ================= device scratch =================
__device__ float g_mean[2][DIM];
__device__ float g_energy[2][DIM];
__device__ float g_var[2][DIM];
__device__ float g_kurt[2][DIM];
__device__ float g_skew[2][DIM];
__device__ float g_rownorm[TWO_N];
__device__ float g_cacc[2][4][DIM];          // raw moment partials S1..S4
__device__ float g_acc[4];                   // 0 mmd-sum, 1 log(p) src, 2 log(1-p) tgt, 3 weight
__device__ __nv_bfloat16 g_ubf[(size_t)TWO_N * DIM];

// ================= helpers =================
__device__ __forceinline__ void cp16(uint32_t dst_smem, const void* src) {
    asm volatile("cp.async.cg.shared.global [%0], [%1], 16;" :: "r"(dst_smem), "l"(src));
}
__device__ __forceinline__ void mma16816(float* c, const uint32_t* a, const uint32_t* b) {
    asm volatile(
        "mma.sync.aligned.m16n8k16.row.col.f32.bf16.bf16.f32 "
        "{%0,%1,%2,%3}, {%4,%5,%6,%7}, {%8,%9}, {%0,%1,%2,%3};"
        : "+f"(c[0]), "+f"(c[1]), "+f"(c[2]), "+f"(c[3])
        : "r"(a[0]), "r"(a[1]), "r"(a[2]), "r"(a[3]), "r"(b[0]), "r"(b[1]));
}
__device__ __forceinline__ void ldm_x4(uint32_t* r, uint32_t addr) {
    asm volatile("ldmatrix.sync.aligned.m8n8.x4.shared.b16 {%0,%1,%2,%3}, [%4];"
        : "=r"(r[0]), "=r"(r[1]), "=r"(r[2]), "=r"(r[3]) : "r"(addr));
}

// ================= init =================
__global__ void k_zero() {
    float* p = &g_cacc[0][0][0];
    for (int i = blockIdx.x * blockDim.x + threadIdx.x; i < 2 * 4 * DIM; i += gridDim.x * blockDim.x)
        p[i] = 0.f;
    if (blockIdx.x == 0 && threadIdx.x < 4) g_acc[threadIdx.x] = 0.f;
}

// ================= fused prep: bf16 convert + rownorm + raw column moments =================
// grid 512, 256 threads, 32 rows of u per block
__global__ void __launch_bounds__(256) k_prep(const float* __restrict__ s,
                                              const float* __restrict__ t) {
    __shared__ float sh_rn[32];
    int tid = threadIdx.x, lane = tid & 31;
    if (tid < 32) sh_rn[tid] = 0.f;
    __syncthreads();

    int row0 = blockIdx.x * 32;
    int tensor = (row0 >= N_ROWS);
    const float* X = tensor ? t + (size_t)(row0 - N_ROWS) * DIM : s + (size_t)row0 * DIM;
    int c4 = tid & 127;          // float4 column index 0..127
    int rg = tid >> 7;           // 0/1

    float M1[4] = {0.f, 0.f, 0.f, 0.f}, M2[4] = {0.f, 0.f, 0.f, 0.f};
    float M3[4] = {0.f, 0.f, 0.f, 0.f}, M4[4] = {0.f, 0.f, 0.f, 0.f};

#pragma unroll 4
    for (int i = 0; i < 16; i++) {
        int r = rg * 16 + i;
        float4 v = ((const float4*)(X + (size_t)r * DIM))[c4];
        __nv_bfloat162* dst = (__nv_bfloat162*)(g_ubf + (size_t)(row0 + r) * DIM);
        dst[c4 * 2]     = __floats2bfloat162_rn(v.x, v.y);
        dst[c4 * 2 + 1] = __floats2bfloat162_rn(v.z, v.w);
        float vv[4] = {v.x, v.y, v.z, v.w};
        float rn = 0.f;
#pragma unroll
        for (int j = 0; j < 4; j++) {
            float x = vv[j], x2 = x * x;
            M1[j] += x; M2[j] += x2; M3[j] += x2 * x; M4[j] += x2 * x2;
            rn += x2;
        }
#pragma unroll
        for (int o = 16; o; o >>= 1) rn += __shfl_xor_sync(0xffffffffu, rn, o);
        if (!lane) atomicAdd(&sh_rn[r], rn);
    }
    __syncthreads();
    if (tid < 32) g_rownorm[row0 + tid] = sh_rn[tid];

#pragma unroll
    for (int j = 0; j < 4; j++) {
        int c = c4 * 4 + j;
        atomicAdd(&g_cacc[tensor][0][c], M1[j]);
        atomicAdd(&g_cacc[tensor][1][c], M2[j]);
        atomicAdd(&g_cacc[tensor][2][c], M3[j]);
        atomicAdd(&g_cacc[tensor][3][c], M4[j]);
    }
}

// ================= central moments from raw moments =================
__global__ void k_colfin() {
    int tensor = blockIdx.x, c = threadIdx.x;
    const float n = (float)N_ROWS;
    float S1 = g_cacc[tensor][0][c], S2 = g_cacc[tensor][1][c];
    float S3 = g_cacc[tensor][2][c], S4 = g_cacc[tensor][3][c];
    float m = S1 / n;
    float c2 = S2 - m * S1;
    float c3 = S3 - 3.f * m * S2 + 2.f * m * m * S1;
    float c4 = S4 - 4.f * m * S3 + 6.f * m * m * S2 - 3.f * m * m * m * S1;
    float var = c2 / (n - 1.f);
    float inv = 1.f / (sqrtf(var) + 1e-8f);
    float inv3 = inv * inv * inv;
    g_mean[tensor][c]   = m;
    g_energy[tensor][c] = S2 / n;
    g_var[tensor][c]    = var;
    g_skew[tensor][c]   = c3 * inv3 / n;
    g_kurt[tensor][c]   = c4 * inv3 * inv / n - 3.f;
}

// ================= stat-diff MLP =================
__global__ void k_statmlp(const float* __restrict__ wW1, const float* __restrict__ wb1,
                          const float* __restrict__ wW2, const float* __restrict__ wb2,
                          const float* __restrict__ wW3, const float* __restrict__ wb3,
                          float* __restrict__ out) {
    __shared__ float red[5][256];
    int tid = threadIdx.x;
    float l[5] = {0.f, 0.f, 0.f, 0.f, 0.f};
    for (int c = tid; c < DIM; c += 256) {
        l[0] += fabsf(g_mean[0][c]   - g_mean[1][c]);
        l[1] += fabsf(g_var[0][c]    - g_var[1][c]);
        l[2] += fabsf(g_kurt[0][c]   - g_kurt[1][c]);
        l[3] += fabsf(g_skew[0][c]   - g_skew[1][c]);
        l[4] += fabsf(g_energy[0][c] - g_energy[1][c]);
    }
#pragma unroll
    for (int k = 0; k < 5; k++) red[k][tid] = l[k];
    __syncthreads();
    for (int stride = 128; stride > 0; stride >>= 1) {
        if (tid < stride)
#pragma unroll
            for (int k = 0; k < 5; k++) red[k][tid] += red[k][tid + stride];
        __syncthreads();
    }
    __shared__ float diff[6], h1[32], h2[16];
    if (tid < 6) diff[tid] = (tid < 5) ? red[tid][0] / (float)DIM : 0.f;
    __syncthreads();
    if (tid < 32) {
        float a = wb1[tid];
#pragma unroll
        for (int k = 0; k < 6; k++) a += diff[k] * wW1[k * 32 + tid];
        h1[tid] = fmaxf(a, 0.f);
    }
    __syncthreads();
    if (tid < 16) {
        float a = wb2[tid];
#pragma unroll
        for (int k = 0; k < 32; k++) a += h1[k] * wW2[k * 16 + tid];
        h2[tid] = fmaxf(a, 0.f);
    }
    __syncthreads();
    if (tid == 0) {
        float z = wb3[0];
#pragma unroll
        for (int k = 0; k < 16; k++) z += h2[k] * wW3[k];
        float wgt = 1.f / (1.f + expf(-z));
        g_acc[3] = wgt;
        out[1] = wgt;
    }
}

// ================= discriminator MLP + BCE =================
#define DR 32
__global__ void __launch_bounds__(256) k_disc(
    const float* __restrict__ s, const float* __restrict__ t,
    const float* __restrict__ W1, const float* __restrict__ b1,
    const float* __restrict__ W2, const float* __restrict__ b2,
    const float* __restrict__ W3, const float* __restrict__ b3) {
    extern __shared__ float dsm[];
    float* xs = dsm;                  // [DR][512]
    float* h1 = dsm + DR * DIM;       // [DR][256]

    int tid = threadIdx.x;
    int blk = blockIdx.x;
    bool srcblk = blk < (N_ROWS / DR);
    const float* X = srcblk ? (s + (size_t)blk * DR * DIM)
                            : (t + (size_t)(blk - N_ROWS / DR) * DR * DIM);
    for (int i = tid; i < DR * DIM / 4; i += 256)
        ((float4*)xs)[i] = ((const float4*)X)[i];
    __syncthreads();

    // layer 1: 512 -> 256
    {
        float acc[DR];
#pragma unroll
        for (int r = 0; r < DR; r++) acc[r] = 0.f;
        for (int k = 0; k < DIM; k += 4) {
            float w0 = W1[(k + 0) * 256 + tid];
            float w1 = W1[(k + 1) * 256 + tid];
            float w2 = W1[(k + 2) * 256 + tid];
            float w3 = W1[(k + 3) * 256 + tid];
#pragma unroll
            for (int r = 0; r < DR; r++) {
                float4 xv = *(const float4*)&xs[r * DIM + k];
                acc[r] += xv.x * w0 + xv.y * w1 + xv.z * w2 + xv.w * w3;
            }
        }
        float bb = b1[tid];
#pragma unroll
        for (int r = 0; r < DR; r++) h1[r * 256 + tid] = fmaxf(acc[r] + bb, 0.f);
    }
    __syncthreads();

    // layer 2: 256 -> 128 (h2 overlays xs)
    float* h2 = dsm;
    if (tid < 128) {
        float acc[DR];
#pragma unroll
        for (int r = 0; r < DR; r++) acc[r] = 0.f;
        for (int k = 0; k < 256; k += 4) {
            float w0 = W2[(k + 0) * 128 + tid];
            float w1 = W2[(k + 1) * 128 + tid];
            float w2 = W2[(k + 2) * 128 + tid];
            float w3 = W2[(k + 3) * 128 + tid];
#pragma unroll
            for (int r = 0; r < DR; r++) {
                float4 hv = *(const float4*)&h1[r * 256 + k];
                acc[r] += hv.x * w0 + hv.y * w1 + hv.z * w2 + hv.w * w3;
            }
        }
        float bb = b2[tid];
#pragma unroll
        for (int r = 0; r < DR; r++) h2[r * 128 + tid] = fmaxf(acc[r] + bb, 0.f);
    }
    __syncthreads();

    // layer 3: 128 -> 1 + sigmoid + clamped log; 8 warps x 4 rows
    int w = tid >> 5, lane = tid & 31;
    float lsum = 0.f;
#pragma unroll
    for (int rr = 0; rr < 4; rr++) {
        int r = w * 4 + rr;
        float v = 0.f;
#pragma unroll
        for (int k = lane; k < 128; k += 32) v += h2[r * 128 + k] * W3[k];
#pragma unroll
        for (int o = 16; o; o >>= 1) v += __shfl_xor_sync(0xffffffffu, v, o);
        if (!lane) {
            float z = v + b3[0];
            float p = 1.f / (1.f + expf(-z));
            lsum += srcblk ? fmaxf(logf(p), -100.f) : fmaxf(logf(1.f - p), -100.f);
        }
    }
    if (!lane) atomicAdd(&g_acc[srcblk ? 1 : 2], lsum);
}

// ================= MMD via mma.sync bf16 Gram (upper triangle) =================
// CTA 128x128 tile, 8 warps (2x4), warp tile 64x32, BK=32 double-buffered cp.async,
// ldmatrix.x4 fragment feeds.
#define AST 40                       // smem row stride (bf16): 80 B, conflict-free
#define STG (128 * AST * 2)          // bytes per stage buffer

__global__ void __launch_bounds__(256, 2) k_mmd_hmma(const float* __restrict__ s,
                                                     const float* __restrict__ t) {
    int by = blockIdx.y, bx = blockIdx.x;
    if (bx < by) return;                     // upper triangle only

    __shared__ __nv_bfloat16 As[2][128 * AST];
    __shared__ __nv_bfloat16 Bs[2][128 * AST];
    __shared__ float rni_s[128], rnj_s[128], rsum[8];

    int tid = threadIdx.x, lane = tid & 31, wid = tid >> 5;
    int wm = wid & 1, wn = wid >> 1;         // warp grid 2 (M) x 4 (N)
    int gid = lane >> 2, tig = lane & 3;
    int arow0 = by * 128, brow0 = bx * 128;

    if (tid < 128) {
        rni_s[tid] = g_rownorm[arow0 + tid];
        rnj_s[tid] = g_rownorm[brow0 + tid];
    }

    uint32_t sA = (uint32_t)__cvta_generic_to_shared(&As[0][0]);
    uint32_t sB = (uint32_t)__cvta_generic_to_shared(&Bs[0][0]);
    const __nv_bfloat16* gA = g_ubf + (size_t)arow0 * DIM;
    const __nv_bfloat16* gB = g_ubf + (size_t)brow0 * DIM;

    // lane-dependent ldmatrix offsets (bytes)
    uint32_t a_lo = (uint32_t)((lane & 15) * (AST * 2) + (lane >> 4) * 16);
    uint32_t b_lo = (uint32_t)(((lane & 7) + ((lane >> 4) * 8)) * (AST * 2) + ((lane >> 3) & 1) * 16);

    float acc[4][4][4];
#pragma unroll
    for (int i = 0; i < 4; i++)
#pragma unroll
        for (int j = 0; j < 4; j++)
#pragma unroll
            for (int e = 0; e < 4; e++) acc[i][j][e] = 0.f;

    auto issue = [&](int kt, int st) {
#pragma unroll
        for (int q = 0; q < 2; q++) {
            int c = tid + q * 256;           // 0..511 16B-chunks
            int row = c >> 2, cg = c & 3;
            size_t goff = (size_t)row * DIM + (size_t)kt * 32 + cg * 8;
            uint32_t soff = (uint32_t)(st * STG + row * (AST * 2) + cg * 16);
            cp16(sA + soff, gA + goff);
            cp16(sB + soff, gB + goff);
        }
        asm volatile("cp.async.commit_group;" ::: "memory");
    };

    issue(0, 0);
    for (int kt = 0; kt < 16; kt++) {
        int st = kt & 1;
        if (kt < 15) {
            issue(kt + 1, st ^ 1);
            asm volatile("cp.async.wait_group 1;" ::: "memory");
        } else {
            asm volatile("cp.async.wait_group 0;" ::: "memory");
        }
        __syncthreads();

        uint32_t aS = sA + st * STG + (uint32_t)(wm * 64) * (AST * 2) + a_lo;
        uint32_t bS = sB + st * STG + (uint32_t)(wn * 32) * (AST * 2) + b_lo;
#pragma unroll
        for (int ks = 0; ks < 2; ks++) {     // two k16 steps per BK=32
            uint32_t kb2 = ks * 32;          // byte offset of k16 step
            uint32_t af[4][4], bf[4][2];
#pragma unroll
            for (int mt = 0; mt < 4; mt++)
                ldm_x4(af[mt], aS + (uint32_t)(mt * 16) * (AST * 2) + kb2);
#pragma unroll
            for (int p = 0; p < 2; p++) {
                uint32_t bq[4];
                ldm_x4(bq, bS + (uint32_t)(p * 16) * (AST * 2) + kb2);
                bf[2 * p][0] = bq[0]; bf[2 * p][1] = bq[1];
                bf[2 * p + 1][0] = bq[2]; bf[2 * p + 1][1] = bq[3];
            }
#pragma unroll
            for (int mt = 0; mt < 4; mt++)
#pragma unroll
                for (int nt = 0; nt < 4; nt++)
                    mma16816(acc[mt][nt], af[mt], bf[nt]);
        }
        __syncthreads();
    }

    // ---- epilogue: gate + (rare) exact fp32 recompute ----
    bool diag = (bx == by);
    float sgn = ((by < 64) == (bx < 64)) ? 1.f : -1.f;
    float local = 0.f;

#pragma unroll
    for (int mt = 0; mt < 4; mt++) {
        int li0 = wm * 64 + mt * 16 + gid;          // local row of c0/c1
        float rn0 = rni_s[li0], rn1 = rni_s[li0 + 8];
#pragma unroll
        for (int nt = 0; nt < 4; nt++) {
            int lj0 = wn * 32 + nt * 8 + 2 * tig;   // local col of c0/c2
#pragma unroll
            for (int e = 0; e < 4; e++) {
                int li = li0 + ((e >= 2) ? 8 : 0);
                int lj = lj0 + (e & 1);
                float rn_i = (e >= 2) ? rn1 : rn0;
                float rj = rnj_s[lj];
                float dot = acc[mt][nt][e];
                float d2 = rn_i + rj - 2.f * dot;
                int gi = arow0 + li, gj = brow0 + lj;
                float wgt = diag ? ((gj > gi) ? 2.f : 0.f) : 2.f;
                if (wgt != 0.f && d2 < 110.f + 0.02f * (rn_i + rj)) {
                    // exact fp32 recompute (hit only by near-duplicate pairs)
                    const float* pi = (gi < N_ROWS) ? s + (size_t)gi * DIM
                                                    : t + (size_t)(gi - N_ROWS) * DIM;
                    const float* pj = (gj < N_ROWS) ? s + (size_t)gj * DIM
                                                    : t + (size_t)(gj - N_ROWS) * DIM;
                    float a2 = 0.f;
                    for (int k = 0; k < DIM; k += 4) {
                        float4 a = *(const float4*)(pi + k);
                        float4 b = *(const float4*)(pj + k);
                        float e0 = a.x - b.x, e1 = a.y - b.y, e2 = a.z - b.z, e3 = a.w - b.w;
                        a2 += e0 * e0 + e1 * e1 + e2 * e2 + e3 * e3;
                    }
                    local += wgt * expf(-0.5f * a2);
                }
            }
        }
    }
    local *= sgn;
#pragma unroll
    for (int o = 16; o; o >>= 1) local += __shfl_xor_sync(0xffffffffu, local, o);
    if (!lane) rsum[wid] = local;
    __syncthreads();
    if (tid == 0) {
        float tot = 0.f;
#pragma unroll
        for (int i = 0; i < 8; i++) tot += rsum[i];
        if (tot != 0.f) atomicAdd(&g_acc[0], tot);
    }
}

// ================= final combine =================
__global__ void k_final(float* __restrict__ out) {
    // + TWO_N: analytic diagonal (d2 == 0 -> exp == 1, weight 1, sign +)
    float mmd = (g_acc[0] + (float)TWO_N) / ((float)N_ROWS * (float)N_ROWS);
    float adv = -g_acc[1] / (float)N_ROWS - g_acc[2] / (float)N_ROWS;
    float w = g_acc[3];
    out[0] = w * mmd + (1.f - w) * adv;
}

// ================= launch =================
extern "C" void kernel_launch(void* const* d_in, const int* in_sizes, int n_in,
                              void* d_out, int out_size) {
    const float* s   = (const float*)d_in[0];
    const float* t   = (const float*)d_in[1];
    const float* dW1 = (const float*)d_in[2];
    const float* db1 = (const float*)d_in[3];
    const float* dW2 = (const float*)d_in[4];
    const float* db2 = (const float*)d_in[5];
    const float* dW3 = (const float*)d_in[6];
    const float* db3 = (const float*)d_in[7];
    const float* wW1 = (const float*)d_in[8];
    const float* wb1 = (const float*)d_in[9];
    const float* wW2 = (const float*)d_in[10];
    const float* wb2 = (const float*)d_in[11];
    const float* wW3 = (const float*)d_in[12];
    const float* wb3 = (const float*)d_in[13];
    float* out = (float*)d_out;

    static int disc_smem = (DR * DIM + DR * 256) * (int)sizeof(float);
    cudaFuncSetAttribute(k_disc, cudaFuncAttributeMaxDynamicSharedMemorySize, disc_smem);

    k_zero<<<8, 256>>>();
    k_prep<<<TWO_N / 32, 256>>>(s, t);
    k_colfin<<<2, 512>>>();
    k_statmlp<<<1, 256>>>(wW1, wb1, wW2, wb2, wW3, wb3, out);
    k_disc<<<TWO_N / DR, 256, disc_smem>>>(s, t, dW1, db1, dW2, db2, dW3, db3);
    k_mmd_hmma<<<dim3(128, 128), 256>>>(s, t);
    k_final<<<1, 1>>>(out);
}